// round 10
// baseline (speedup 1.0000x reference)
#include <cuda_runtime.h>
#include <cstdint>

// Problem constants (fixed by the dataset: V=8192 vertices, E=40000 tets)
#define V 8192
#define E 40000
#define E_BLOCKS ((E + 255) / 256)

#define ROWS_PER_BLOCK 4
#define COL_SPLIT 2                        // each block covers V/COL_SPLIT columns
#define COLS_PER_BLOCK (V / COL_SPLIT)     // 4096 columns
#define MV_ITERS ((COLS_PER_BLOCK / 4) / 256)   // 4 float4-iterations
#define MV_BLOCKS ((V / ROWS_PER_BLOCK) * COL_SPLIT)  // 4096 blocks

// Scratch (device globals — no allocations allowed). 16B-aligned for float4 LDG.
__device__ __align__(16) float g_dx[V];
__device__ __align__(16) float g_dy[V];
__device__ __align__(16) float g_dz[V];
__device__ double g_kin_accum;    // sum_i delta_i . (M delta)_i   (atomic)
__device__ double g_el_accum;     // sum_e psi_e * measure_e       (atomic)
__device__ unsigned int g_ticket; // matvec completion counter

// ---------------------------------------------------------------------------
// Kernel 1 (fused prologue): elastic energy per element + delta computation.
// elements is int32 on device (JAX x64 disabled); clamped defensively.
// ---------------------------------------------------------------------------
__global__ __launch_bounds__(256) void prologue_kernel(
    const float* __restrict__ next_pos,
    const float* __restrict__ pos,
    const float* __restrict__ vel,
    const float* __restrict__ ext,
    const float* __restrict__ ts_ptr,
    const int* __restrict__ elems,
    const float* __restrict__ poly,
    const float* __restrict__ measure,
    const float* __restrict__ lam,
    const float* __restrict__ mu)
{
    int gid = blockIdx.x * blockDim.x + threadIdx.x;

    if (gid == 0) {
        g_kin_accum = 0.0;
        g_el_accum  = 0.0;
        g_ticket    = 0u;
    }

    // --- delta part (first V threads) ---
    if (gid < V) {
        float dt  = ts_ptr[0];
        float dt2 = dt * dt;
        int b = gid * 3;
        g_dx[gid] = next_pos[b + 0] - (pos[b + 0] + vel[b + 0] * dt + ext[b + 0] * dt2);
        g_dy[gid] = next_pos[b + 1] - (pos[b + 1] + vel[b + 1] * dt + ext[b + 1] * dt2);
        g_dz[gid] = next_pos[b + 2] - (pos[b + 2] + vel[b + 2] * dt + ext[b + 2] * dt2);
    }

    // --- elastic part ---
    float val = 0.f;
    if (gid < E) {
        int e = gid;
        float F00 = 0.f, F01 = 0.f, F02 = 0.f;
        float F10 = 0.f, F11 = 0.f, F12 = 0.f;
        float F20 = 0.f, F21 = 0.f, F22 = 0.f;
        const int4 ev = reinterpret_cast<const int4*>(elems)[e];
        int vidx[4] = { ev.x, ev.y, ev.z, ev.w };
        const float4* __restrict__ pl4 = reinterpret_cast<const float4*>(poly) + (size_t)e * 4;
#pragma unroll
        for (int f = 0; f < 4; ++f) {
            int vi = vidx[f];
            vi = vi < 0 ? 0 : (vi >= V ? V - 1 : vi);   // defensive clamp
            const float* p = next_pos + (size_t)vi * 3;
            float px = p[0], py = p[1], pz = p[2];
            float4 pl = pl4[f];
            float p0 = pl.x, p1 = pl.y, p2 = pl.z;
            F00 += px * p0; F01 += px * p1; F02 += px * p2;
            F10 += py * p0; F11 += py * p1; F12 += py * p2;
            F20 += pz * p0; F21 += pz * p1; F22 += pz * p2;
        }
        float Ic = F00*F00 + F01*F01 + F02*F02
                 + F10*F10 + F11*F11 + F12*F12
                 + F20*F20 + F21*F21 + F22*F22;
        float J = F00 * (F11 * F22 - F12 * F21)
                - F01 * (F10 * F22 - F12 * F20)
                + F02 * (F10 * F21 - F11 * F20);
        float l = lam[e], m = mu[e];
        float alpha = 0.75f * m / l + 1.0f;
        float Icv = fmaxf(Ic + 1.0f, 0.0f);
        float d = J - alpha;
        float psi = 0.5f * m * (Ic - 3.0f)
                  + 0.5f * l * d * d
                  - 0.5f * m * logf(Icv + 1e-30f);
        val = psi * measure[(size_t)e * 4 + 3];
    }

#pragma unroll
    for (int off = 16; off > 0; off >>= 1)
        val += __shfl_down_sync(0xFFFFFFFFu, val, off);
    __shared__ float sh[8];
    int lane = threadIdx.x & 31;
    int warp = threadIdx.x >> 5;
    if (lane == 0) sh[warp] = val;
    __syncthreads();
    if (threadIdx.x == 0) {
        float s = 0.f;
#pragma unroll
        for (int w = 0; w < 8; ++w) s += sh[w];
        atomicAdd(&g_el_accum, (double)s);
    }
}

// ---------------------------------------------------------------------------
// Kernel 2: weighted matrix reduction (delta^T M delta summed over x/y/z).
// No per-row output is needed, so work is tiled 4 rows x 4096 columns per
// block (grid 4096). M loads use an explicit 2-deep register pipeline so
// 4-8 independent M lines are in flight per warp regardless of ptxas
// scheduling; M is streamed with __ldcs. Last block (ticket) writes outputs.
// ---------------------------------------------------------------------------
__global__ __launch_bounds__(256) void matvec_kernel(const float* __restrict__ M,
                                                     const float* __restrict__ ts_ptr,
                                                     float* __restrict__ out)
{
    const int tile  = blockIdx.x;
    const int row0  = (tile / COL_SPLIT) * ROWS_PER_BLOCK;
    const int cseg  = tile % COL_SPLIT;              // column segment
    const int cbase = cseg * (COLS_PER_BLOCK / 4);   // in float4 units

    const float4* __restrict__ M0 = reinterpret_cast<const float4*>(M + (size_t)(row0 + 0) * V) + cbase;
    const float4* __restrict__ M1 = reinterpret_cast<const float4*>(M + (size_t)(row0 + 1) * V) + cbase;
    const float4* __restrict__ M2 = reinterpret_cast<const float4*>(M + (size_t)(row0 + 2) * V) + cbase;
    const float4* __restrict__ M3 = reinterpret_cast<const float4*>(M + (size_t)(row0 + 3) * V) + cbase;
    const float4* __restrict__ DX = reinterpret_cast<const float4*>(g_dx) + cbase;
    const float4* __restrict__ DY = reinterpret_cast<const float4*>(g_dy) + cbase;
    const float4* __restrict__ DZ = reinterpret_cast<const float4*>(g_dz) + cbase;

    float a00=0.f,a01=0.f,a02=0.f, a10=0.f,a11=0.f,a12=0.f;
    float a20=0.f,a21=0.f,a22=0.f, a30=0.f,a31=0.f,a32=0.f;

    // prologue of the 2-deep pipeline
    int idx0 = threadIdx.x;
    float4 m0 = __ldcs(&M0[idx0]);
    float4 m1 = __ldcs(&M1[idx0]);
    float4 m2 = __ldcs(&M2[idx0]);
    float4 m3 = __ldcs(&M3[idx0]);

#pragma unroll
    for (int it = 0; it < MV_ITERS; ++it) {
        int idx  = threadIdx.x + it * 256;
        int nidx = idx + 256;
        float4 n0, n1, n2, n3;
        if (it + 1 < MV_ITERS) {
            n0 = __ldcs(&M0[nidx]);
            n1 = __ldcs(&M1[nidx]);
            n2 = __ldcs(&M2[nidx]);
            n3 = __ldcs(&M3[nidx]);
        }
        float4 x = DX[idx];
        float4 y = DY[idx];
        float4 z = DZ[idx];

        a00 += m0.x*x.x + m0.y*x.y + m0.z*x.z + m0.w*x.w;
        a01 += m0.x*y.x + m0.y*y.y + m0.z*y.z + m0.w*y.w;
        a02 += m0.x*z.x + m0.y*z.y + m0.z*z.z + m0.w*z.w;

        a10 += m1.x*x.x + m1.y*x.y + m1.z*x.z + m1.w*x.w;
        a11 += m1.x*y.x + m1.y*y.y + m1.z*y.z + m1.w*y.w;
        a12 += m1.x*z.x + m1.y*z.y + m1.z*z.z + m1.w*z.w;

        a20 += m2.x*x.x + m2.y*x.y + m2.z*x.z + m2.w*x.w;
        a21 += m2.x*y.x + m2.y*y.y + m2.z*y.z + m2.w*y.w;
        a22 += m2.x*z.x + m2.y*z.y + m2.z*z.z + m2.w*z.w;

        a30 += m3.x*x.x + m3.y*x.y + m3.z*x.z + m3.w*x.w;
        a31 += m3.x*y.x + m3.y*y.y + m3.z*y.z + m3.w*y.w;
        a32 += m3.x*z.x + m3.y*z.y + m3.z*z.z + m3.w*z.w;

        m0 = n0; m1 = n1; m2 = n2; m3 = n3;
    }

    // reduce 12 partials: warp shuffles then smem
#pragma unroll
    for (int off = 16; off > 0; off >>= 1) {
        a00 += __shfl_down_sync(0xFFFFFFFFu, a00, off);
        a01 += __shfl_down_sync(0xFFFFFFFFu, a01, off);
        a02 += __shfl_down_sync(0xFFFFFFFFu, a02, off);
        a10 += __shfl_down_sync(0xFFFFFFFFu, a10, off);
        a11 += __shfl_down_sync(0xFFFFFFFFu, a11, off);
        a12 += __shfl_down_sync(0xFFFFFFFFu, a12, off);
        a20 += __shfl_down_sync(0xFFFFFFFFu, a20, off);
        a21 += __shfl_down_sync(0xFFFFFFFFu, a21, off);
        a22 += __shfl_down_sync(0xFFFFFFFFu, a22, off);
        a30 += __shfl_down_sync(0xFFFFFFFFu, a30, off);
        a31 += __shfl_down_sync(0xFFFFFFFFu, a31, off);
        a32 += __shfl_down_sync(0xFFFFFFFFu, a32, off);
    }
    __shared__ float sh[12][8];
    int lane = threadIdx.x & 31;
    int warp = threadIdx.x >> 5;
    if (lane == 0) {
        sh[0][warp]=a00; sh[1][warp]=a01; sh[2][warp]=a02;
        sh[3][warp]=a10; sh[4][warp]=a11; sh[5][warp]=a12;
        sh[6][warp]=a20; sh[7][warp]=a21; sh[8][warp]=a22;
        sh[9][warp]=a30; sh[10][warp]=a31; sh[11][warp]=a32;
    }
    __syncthreads();

    if (threadIdx.x < 12) {
        float s = 0.f;
#pragma unroll
        for (int w = 0; w < 8; ++w) s += sh[threadIdx.x][w];
        sh[threadIdx.x][0] = s;
    }
    __syncthreads();

    if (threadIdx.x == 0) {
        double contrib = 0.0;
#pragma unroll
        for (int r = 0; r < ROWS_PER_BLOCK; ++r) {
            int row = row0 + r;
            contrib += (double)g_dx[row] * sh[r*3+0][0]
                     + (double)g_dy[row] * sh[r*3+1][0]
                     + (double)g_dz[row] * sh[r*3+2][0];
        }
        atomicAdd(&g_kin_accum, contrib);

        __threadfence();
        unsigned int t = atomicAdd(&g_ticket, 1u);
        if (t == (unsigned int)(MV_BLOCKS - 1)) {
            // all kinetic atomics visible; elastic finished (stream order)
            double dt = (double)ts_ptr[0];
            double inv_h = 1.0 / dt;
            double coeff = inv_h * inv_h * 0.5;
            double kin = coeff * g_kin_accum;
            double el  = g_el_accum;
            out[0] = (float)(kin + el);
            out[1] = (float)kin;
            out[2] = (float)el;
        }
    }
}

// ---------------------------------------------------------------------------
// Launch
// ---------------------------------------------------------------------------
extern "C" void kernel_launch(void* const* d_in, const int* in_sizes, int n_in,
                              void* d_out, int out_size)
{
    const float* next_pos = (const float*)d_in[0];
    const float* pos      = (const float*)d_in[1];
    const float* vel      = (const float*)d_in[2];
    const float* ext      = (const float*)d_in[3];
    const float* M        = (const float*)d_in[4];
    const int*   elems    = (const int*)d_in[5];
    const float* poly     = (const float*)d_in[6];
    const float* measure  = (const float*)d_in[7];
    const float* lam      = (const float*)d_in[8];
    const float* mu       = (const float*)d_in[9];
    const float* ts       = (const float*)d_in[10];
    float* out = (float*)d_out;

    prologue_kernel<<<E_BLOCKS, 256>>>(next_pos, pos, vel, ext, ts,
                                       elems, poly, measure, lam, mu);
    matvec_kernel<<<MV_BLOCKS, 256>>>(M, ts, out);
}

// round 11
// speedup vs baseline: 1.4740x; 1.4740x over previous
#include <cuda_runtime.h>
#include <cstdint>

// Problem constants (fixed by the dataset: V=8192 vertices, E=40000 tets)
#define V 8192
#define E 40000
#define E_BLOCKS ((E + 255) / 256)
#define ROWS_PER_BLOCK 4
#define MV_BLOCKS (V / ROWS_PER_BLOCK)   // 2048

// Scratch (device globals — no allocations allowed). 16B-aligned for float4 LDG.
__device__ __align__(16) float g_dx[V];
__device__ __align__(16) float g_dy[V];
__device__ __align__(16) float g_dz[V];
__device__ double g_kin_accum;    // sum_i delta_i . (M delta)_i   (atomic)
__device__ double g_el_accum;     // sum_e psi_e * measure_e       (atomic)
__device__ unsigned int g_ticket; // matvec completion counter

// ---------------------------------------------------------------------------
// Kernel 1 (fused prologue): elastic energy per element + delta computation.
//   first V threads: delta = next_pos - (pos + vel*dt + ext*dt^2)  (SoA)
//   all e < E:       psi(F(e)) * measure[e][3][0], block-reduced + atomic
// elements is int32 on device (JAX x64 disabled); clamped defensively.
// ---------------------------------------------------------------------------
__global__ __launch_bounds__(256) void prologue_kernel(
    const float* __restrict__ next_pos,
    const float* __restrict__ pos,
    const float* __restrict__ vel,
    const float* __restrict__ ext,
    const float* __restrict__ ts_ptr,
    const int* __restrict__ elems,
    const float* __restrict__ poly,
    const float* __restrict__ measure,
    const float* __restrict__ lam,
    const float* __restrict__ mu)
{
    int gid = blockIdx.x * blockDim.x + threadIdx.x;

    if (gid == 0) {
        g_kin_accum = 0.0;
        g_el_accum  = 0.0;
        g_ticket    = 0u;
    }

    // --- delta part (first V threads) ---
    if (gid < V) {
        float dt  = ts_ptr[0];
        float dt2 = dt * dt;
        int b = gid * 3;
        g_dx[gid] = next_pos[b + 0] - (pos[b + 0] + vel[b + 0] * dt + ext[b + 0] * dt2);
        g_dy[gid] = next_pos[b + 1] - (pos[b + 1] + vel[b + 1] * dt + ext[b + 1] * dt2);
        g_dz[gid] = next_pos[b + 2] - (pos[b + 2] + vel[b + 2] * dt + ext[b + 2] * dt2);
    }

    // --- elastic part ---
    float val = 0.f;
    if (gid < E) {
        int e = gid;
        float F00 = 0.f, F01 = 0.f, F02 = 0.f;
        float F10 = 0.f, F11 = 0.f, F12 = 0.f;
        float F20 = 0.f, F21 = 0.f, F22 = 0.f;
        const int4 ev = reinterpret_cast<const int4*>(elems)[e];
        int vidx[4] = { ev.x, ev.y, ev.z, ev.w };
        const float4* __restrict__ pl4 = reinterpret_cast<const float4*>(poly) + (size_t)e * 4;
#pragma unroll
        for (int f = 0; f < 4; ++f) {
            int vi = vidx[f];
            vi = vi < 0 ? 0 : (vi >= V ? V - 1 : vi);   // defensive clamp
            const float* p = next_pos + (size_t)vi * 3;
            float px = p[0], py = p[1], pz = p[2];
            float4 pl = pl4[f];
            float p0 = pl.x, p1 = pl.y, p2 = pl.z;
            F00 += px * p0; F01 += px * p1; F02 += px * p2;
            F10 += py * p0; F11 += py * p1; F12 += py * p2;
            F20 += pz * p0; F21 += pz * p1; F22 += pz * p2;
        }
        float Ic = F00*F00 + F01*F01 + F02*F02
                 + F10*F10 + F11*F11 + F12*F12
                 + F20*F20 + F21*F21 + F22*F22;
        float J = F00 * (F11 * F22 - F12 * F21)
                - F01 * (F10 * F22 - F12 * F20)
                + F02 * (F10 * F21 - F11 * F20);
        float l = lam[e], m = mu[e];
        float alpha = 0.75f * m / l + 1.0f;
        float Icv = fmaxf(Ic + 1.0f, 0.0f);
        float d = J - alpha;
        float psi = 0.5f * m * (Ic - 3.0f)
                  + 0.5f * l * d * d
                  - 0.5f * m * logf(Icv + 1e-30f);
        val = psi * measure[(size_t)e * 4 + 3];
    }

#pragma unroll
    for (int off = 16; off > 0; off >>= 1)
        val += __shfl_down_sync(0xFFFFFFFFu, val, off);
    __shared__ float sh[8];
    int lane = threadIdx.x & 31;
    int warp = threadIdx.x >> 5;
    if (lane == 0) sh[warp] = val;
    __syncthreads();
    if (threadIdx.x == 0) {
        float s = 0.f;
#pragma unroll
        for (int w = 0; w < 8; ++w) s += sh[w];
        atomicAdd(&g_el_accum, (double)s);
    }
}

// ---------------------------------------------------------------------------
// Kernel 2: matvec + dot, 4 full rows per block (best-measured shape).
// __launch_bounds__(256, 5) caps registers at 48 -> 5 blocks/SM (40 warps),
// raising in-flight M lines ~1.7x vs the 3-4 block/SM variants.
// M streamed with __ldcs; delta stays L1-resident (L1 persists across CTAs
// within a launch). Last block (ticket) writes the outputs.
// ---------------------------------------------------------------------------
__global__ __launch_bounds__(256, 5) void matvec_kernel(const float* __restrict__ M,
                                                        const float* __restrict__ ts_ptr,
                                                        float* __restrict__ out)
{
    const int row0 = blockIdx.x * ROWS_PER_BLOCK;
    const float4* __restrict__ M0 = reinterpret_cast<const float4*>(M + (size_t)(row0 + 0) * V);
    const float4* __restrict__ M1 = reinterpret_cast<const float4*>(M + (size_t)(row0 + 1) * V);
    const float4* __restrict__ M2 = reinterpret_cast<const float4*>(M + (size_t)(row0 + 2) * V);
    const float4* __restrict__ M3 = reinterpret_cast<const float4*>(M + (size_t)(row0 + 3) * V);
    const float4* __restrict__ DX = reinterpret_cast<const float4*>(g_dx);
    const float4* __restrict__ DY = reinterpret_cast<const float4*>(g_dy);
    const float4* __restrict__ DZ = reinterpret_cast<const float4*>(g_dz);

    float a00=0.f,a01=0.f,a02=0.f, a10=0.f,a11=0.f,a12=0.f;
    float a20=0.f,a21=0.f,a22=0.f, a30=0.f,a31=0.f,a32=0.f;

#pragma unroll
    for (int it = 0; it < (V / 4) / 256; ++it) {
        int idx = threadIdx.x + it * 256;
        float4 m0 = __ldcs(&M0[idx]);
        float4 m1 = __ldcs(&M1[idx]);
        float4 m2 = __ldcs(&M2[idx]);
        float4 m3 = __ldcs(&M3[idx]);
        float4 x  = DX[idx];
        float4 y  = DY[idx];
        float4 z  = DZ[idx];

        a00 += m0.x*x.x + m0.y*x.y + m0.z*x.z + m0.w*x.w;
        a01 += m0.x*y.x + m0.y*y.y + m0.z*y.z + m0.w*y.w;
        a02 += m0.x*z.x + m0.y*z.y + m0.z*z.z + m0.w*z.w;

        a10 += m1.x*x.x + m1.y*x.y + m1.z*x.z + m1.w*x.w;
        a11 += m1.x*y.x + m1.y*y.y + m1.z*y.z + m1.w*y.w;
        a12 += m1.x*z.x + m1.y*z.y + m1.z*z.z + m1.w*z.w;

        a20 += m2.x*x.x + m2.y*x.y + m2.z*x.z + m2.w*x.w;
        a21 += m2.x*y.x + m2.y*y.y + m2.z*y.z + m2.w*y.w;
        a22 += m2.x*z.x + m2.y*z.y + m2.z*z.z + m2.w*z.w;

        a30 += m3.x*x.x + m3.y*x.y + m3.z*x.z + m3.w*x.w;
        a31 += m3.x*y.x + m3.y*y.y + m3.z*y.z + m3.w*y.w;
        a32 += m3.x*z.x + m3.y*z.y + m3.z*z.z + m3.w*z.w;
    }

    // reduce 12 partials: warp shuffles then smem
#pragma unroll
    for (int off = 16; off > 0; off >>= 1) {
        a00 += __shfl_down_sync(0xFFFFFFFFu, a00, off);
        a01 += __shfl_down_sync(0xFFFFFFFFu, a01, off);
        a02 += __shfl_down_sync(0xFFFFFFFFu, a02, off);
        a10 += __shfl_down_sync(0xFFFFFFFFu, a10, off);
        a11 += __shfl_down_sync(0xFFFFFFFFu, a11, off);
        a12 += __shfl_down_sync(0xFFFFFFFFu, a12, off);
        a20 += __shfl_down_sync(0xFFFFFFFFu, a20, off);
        a21 += __shfl_down_sync(0xFFFFFFFFu, a21, off);
        a22 += __shfl_down_sync(0xFFFFFFFFu, a22, off);
        a30 += __shfl_down_sync(0xFFFFFFFFu, a30, off);
        a31 += __shfl_down_sync(0xFFFFFFFFu, a31, off);
        a32 += __shfl_down_sync(0xFFFFFFFFu, a32, off);
    }
    __shared__ float sh[12][8];
    int lane = threadIdx.x & 31;
    int warp = threadIdx.x >> 5;
    if (lane == 0) {
        sh[0][warp]=a00; sh[1][warp]=a01; sh[2][warp]=a02;
        sh[3][warp]=a10; sh[4][warp]=a11; sh[5][warp]=a12;
        sh[6][warp]=a20; sh[7][warp]=a21; sh[8][warp]=a22;
        sh[9][warp]=a30; sh[10][warp]=a31; sh[11][warp]=a32;
    }
    __syncthreads();

    if (threadIdx.x < 12) {
        float s = 0.f;
#pragma unroll
        for (int w = 0; w < 8; ++w) s += sh[threadIdx.x][w];
        sh[threadIdx.x][0] = s;
    }
    __syncthreads();

    if (threadIdx.x == 0) {
        double contrib = 0.0;
#pragma unroll
        for (int r = 0; r < ROWS_PER_BLOCK; ++r) {
            int row = row0 + r;
            contrib += (double)g_dx[row] * sh[r*3+0][0]
                     + (double)g_dy[row] * sh[r*3+1][0]
                     + (double)g_dz[row] * sh[r*3+2][0];
        }
        atomicAdd(&g_kin_accum, contrib);

        __threadfence();
        unsigned int t = atomicAdd(&g_ticket, 1u);
        if (t == (unsigned int)(MV_BLOCKS - 1)) {
            // all kinetic atomics visible; elastic finished (stream order)
            double dt = (double)ts_ptr[0];
            double inv_h = 1.0 / dt;
            double coeff = inv_h * inv_h * 0.5;
            double kin = coeff * g_kin_accum;
            double el  = g_el_accum;
            out[0] = (float)(kin + el);
            out[1] = (float)kin;
            out[2] = (float)el;
        }
    }
}

// ---------------------------------------------------------------------------
// Launch
// ---------------------------------------------------------------------------
extern "C" void kernel_launch(void* const* d_in, const int* in_sizes, int n_in,
                              void* d_out, int out_size)
{
    const float* next_pos = (const float*)d_in[0];
    const float* pos      = (const float*)d_in[1];
    const float* vel      = (const float*)d_in[2];
    const float* ext      = (const float*)d_in[3];
    const float* M        = (const float*)d_in[4];
    const int*   elems    = (const int*)d_in[5];
    const float* poly     = (const float*)d_in[6];
    const float* measure  = (const float*)d_in[7];
    const float* lam      = (const float*)d_in[8];
    const float* mu       = (const float*)d_in[9];
    const float* ts       = (const float*)d_in[10];
    float* out = (float*)d_out;

    prologue_kernel<<<E_BLOCKS, 256>>>(next_pos, pos, vel, ext, ts,
                                       elems, poly, measure, lam, mu);
    matvec_kernel<<<MV_BLOCKS, 256>>>(M, ts, out);
}